// round 8
// baseline (speedup 1.0000x reference)
#include <cuda_runtime.h>
#include <math.h>

typedef unsigned long long ull;

#define BB   32
#define CIN  64
#define TT   512
#define FF   256
#define GG   8
#define HH   512
#define G4   2048
#define NCLS 50
#define RNB  128
#define NSLOT (TT + 2)
#define PLSZ (4 * 16 * 33)          // partials per layer (floats)

// ------------------------- scratch -----------------------------------------
__device__ float   g_conv[BB * FF * TT];
__device__ float   g_xt[BB * TT * FF];
__device__ float   g_xp[BB * TT * G4];
__device__ float   g_hb1[2][BB * HH];    // [parity][b*HH + unit]
__device__ float   g_hb2[2][BB * HH];
__device__ float   g_hb3[2][BB * HH];
__device__ float   g_feat[BB * HH];
__device__ float2  g_stat[BB * GG];
__device__ int     g_flags[RNB];
__device__ unsigned g_gen2;

// ------------------------- helpers -----------------------------------------
__device__ __forceinline__ void fma2(ull& d, ull a, ull b) {
    asm("fma.rn.f32x2 %0, %1, %2, %0;" : "+l"(d) : "l"(a), "l"(b));
}
union UF2 { ull u; float2 f; };
#define CP_ASYNC16(dst_u32, src_ptr) \
    asm volatile("cp.async.cg.shared.global [%0], [%1], 16;" \
                 :: "r"(dst_u32), "l"(src_ptr))
#define CP_COMMIT() asm volatile("cp.async.commit_group;")
#define CP_WAIT(n)  asm volatile("cp.async.wait_group " #n ";" ::: "memory")

// ------------------------------- conv1d ------------------------------------
#define CONV_SMEM ((64 * 136 + 8 * 64 * 9) * 4)
__global__ __launch_bounds__(256) void conv_kernel(
    const float* __restrict__ x, const float* __restrict__ w)
{
    extern __shared__ float sm[];
    float* xs = sm;
    float* ws = sm + 64 * 136;
    const int b   = blockIdx.y;
    const int t0  = blockIdx.x * 128;
    const int tid = threadIdx.x;

    for (int i = tid; i < 64 * 136; i += 256) {
        int c = i / 136, j = i - c * 136;
        int t = t0 - 4 + j;
        xs[i] = (t >= 0 && t < TT) ? x[(b * CIN + c) * TT + t] : 0.f;
    }
    const int lane = tid & 31;
    const int wf   = tid >> 5;
    const int tl   = lane * 4;

    for (int fc = 0; fc < FF; fc += 8) {
        __syncthreads();
        for (int i = tid; i < 8 * 64 * 9; i += 256)
            ws[i] = w[fc * 64 * 9 + i];
        __syncthreads();
        const int f = fc + wf;
        float a0 = 0.f, a1 = 0.f, a2 = 0.f, a3 = 0.f;
        for (int c = 0; c < 64; ++c) {
            const float* xr = &xs[c * 136 + tl];
            const float* wr = &ws[(wf * 64 + c) * 9];
            float4 p0 = *(const float4*)(xr);
            float4 p1 = *(const float4*)(xr + 4);
            float4 p2 = *(const float4*)(xr + 8);
            float xv[12] = {p0.x, p0.y, p0.z, p0.w, p1.x, p1.y, p1.z, p1.w,
                            p2.x, p2.y, p2.z, p2.w};
#pragma unroll
            for (int k = 0; k < 9; ++k) {
                float wk = wr[k];
                a0 += wk * xv[k];
                a1 += wk * xv[k + 1];
                a2 += wk * xv[k + 2];
                a3 += wk * xv[k + 3];
            }
        }
        *(float4*)&g_conv[(b * FF + f) * TT + t0 + tl] =
            make_float4(a0, a1, a2, a3);
    }
}

// ------------------------------ groupnorm -----------------------------------
__global__ __launch_bounds__(256) void gn_stats_kernel()
{
    const int b = blockIdx.x >> 3, g = blockIdx.x & 7;
    __shared__ float ssum[256], ssq[256];
    const int tid = threadIdx.x;
    const float* base = g_conv + (b * FF + g * 32) * TT;
    float s = 0.f, q = 0.f;
    for (int i = tid; i < 32 * TT; i += 256) {
        float v = base[i];
        s += v; q += v * v;
    }
    ssum[tid] = s; ssq[tid] = q;
    __syncthreads();
    for (int o = 128; o > 0; o >>= 1) {
        if (tid < o) { ssum[tid] += ssum[tid + o]; ssq[tid] += ssq[tid + o]; }
        __syncthreads();
    }
    if (tid == 0) {
        float mean = ssum[0] * (1.f / 16384.f);
        float var  = ssq[0] * (1.f / 16384.f) - mean * mean;
        g_stat[b * GG + g] = make_float2(mean, rsqrtf(var + 1e-5f));
    }
}

__global__ __launch_bounds__(256) void gn_apply_kernel(
    const float* __restrict__ gamma, const float* __restrict__ beta)
{
    __shared__ float tile[32][33];
    const int b  = blockIdx.z;
    const int f0 = blockIdx.y * 32;
    const int t0 = blockIdx.x * 32;
    const int tx = threadIdx.x & 31, ty = threadIdx.x >> 5;
#pragma unroll
    for (int j = 0; j < 4; ++j) {
        int f = f0 + ty + j * 8;
        float2 st = g_stat[b * GG + (f >> 5)];
        float v = g_conv[(b * FF + f) * TT + t0 + tx];
        v = (v - st.x) * st.y * gamma[f] + beta[f];
        tile[ty + j * 8][tx] = fmaxf(v, 0.f);
    }
    __syncthreads();
#pragma unroll
    for (int j = 0; j < 4; ++j) {
        int t = t0 + ty + j * 8;
        g_xt[(b * TT + t) * FF + f0 + tx] = tile[tx][ty + j * 8];
    }
}

// --------------------- projection GEMM (layer 1) ----------------------------
__global__ __launch_bounds__(256) void gemm_kernel(
    const float* __restrict__ A, const float* __restrict__ Bm,
    const float* __restrict__ bias, float* __restrict__ C, int Ka)
{
    __shared__ float As[16][64];
    __shared__ float Bs[16][64];
    const int bm = blockIdx.y * 64, bn = blockIdx.x * 64;
    const int tid = threadIdx.x;
    const int lm  = tid >> 2;
    const int lk4 = (tid & 3) * 4;
    const int tm  = (tid & 15) * 4;
    const int tn  = (tid >> 4) * 4;

    float acc[4][4];
#pragma unroll
    for (int i = 0; i < 4; ++i)
#pragma unroll
        for (int j = 0; j < 4; ++j) acc[i][j] = 0.f;

    for (int ko = 0; ko < Ka; ko += 16) {
        float4 av = *(const float4*)&A[(bm + lm) * Ka + ko + lk4];
        float4 bv = *(const float4*)&Bm[(bn + lm) * Ka + ko + lk4];
        __syncthreads();
        As[lk4 + 0][lm] = av.x; As[lk4 + 1][lm] = av.y;
        As[lk4 + 2][lm] = av.z; As[lk4 + 3][lm] = av.w;
        Bs[lk4 + 0][lm] = bv.x; Bs[lk4 + 1][lm] = bv.y;
        Bs[lk4 + 2][lm] = bv.z; Bs[lk4 + 3][lm] = bv.w;
        __syncthreads();
#pragma unroll
        for (int k = 0; k < 16; ++k) {
            float4 a4 = *(const float4*)&As[k][tm];
            float4 b4 = *(const float4*)&Bs[k][tn];
            float am[4] = {a4.x, a4.y, a4.z, a4.w};
            float bn4[4] = {b4.x, b4.y, b4.z, b4.w};
#pragma unroll
            for (int i = 0; i < 4; ++i)
#pragma unroll
                for (int j = 0; j < 4; ++j) acc[i][j] += am[i] * bn4[j];
        }
    }
#pragma unroll
    for (int i = 0; i < 4; ++i) {
        int row = bm + tm + i;
#pragma unroll
        for (int j = 0; j < 4; ++j)
            C[row * G4 + bn + tn + j] = acc[i][j] + bias[bn + tn + j];
    }
}

// --------------- zero h buffers + reset barrier state -----------------------
__global__ void zero_h_kernel()
{
    int i = blockIdx.x * 256 + threadIdx.x;   // grid 128 -> 32768 (both parities)
    ((float*)g_hb1)[i] = 0.f;
    ((float*)g_hb2)[i] = 0.f;
    ((float*)g_hb3)[i] = 0.f;
    if (blockIdx.x == 0) {
        if (threadIdx.x < RNB) g_flags[threadIdx.x] = 0;
        if (threadIdx.x == 0)  g_gen2 = 0u;
    }
}

// ------------------------- flag-array grid barrier --------------------------
__device__ __forceinline__ void grid_bar2(int slot)
{
    __syncthreads();
    const int tid = threadIdx.x;
    if (tid == 0) {
        __threadfence();
        ((volatile int*)g_flags)[blockIdx.x] = slot + 1;
    }
    if (blockIdx.x == 0) {
        if (tid < RNB)
            while (((volatile int*)g_flags)[tid] <= slot) __nanosleep(32);
        __syncthreads();
        if (tid == 0) {
            __threadfence();
            *((volatile unsigned*)&g_gen2) = (unsigned)(slot + 1);
        }
    } else {
        if (tid == 0)
            while (*((volatile unsigned*)&g_gen2) <= (unsigned)slot)
                __nanosleep(32);
    }
    __syncthreads();
}

// --------- per-thread GEMM: 4 rows x 1 batch, k-packed, w prefetch ----------
__device__ __forceinline__ void gphase(ull acc[4],
    const float* __restrict__ wbase, const float* __restrict__ hrow,
    int swz, int ng)
{
    acc[0] = acc[1] = acc[2] = acc[3] = 0ull;
    ulonglong2 w[4], wn[4];
#pragma unroll
    for (int i = 0; i < 4; ++i)
        w[i] = __ldg((const ulonglong2*)(wbase + i * 512));
#pragma unroll 4
    for (int l = 0; l < ng; ++l) {
        const bool more = (l + 1 < ng);
        if (more) {
#pragma unroll
            for (int i = 0; i < 4; ++i)
                wn[i] = __ldg((const ulonglong2*)(wbase + i * 512 + (l + 1) * 4));
        }
        const int lp = ((l & ~7) | ((l & 7) ^ swz)) * 4;
        ulonglong2 hv = *(const ulonglong2*)(hrow + lp);
#pragma unroll
        for (int i = 0; i < 4; ++i) {
            fma2(acc[i], w[i].x, hv.x);
            fma2(acc[i], w[i].y, hv.y);
        }
        if (more) {
#pragma unroll
            for (int i = 0; i < 4; ++i) w[i] = wn[i];
        }
    }
}

__device__ __forceinline__ void store_part4(float* pl, ull acc[4],
                                            int ks, int rq, int bp)
{
#pragma unroll
    for (int i = 0; i < 4; ++i) {
        UF2 t; t.u = acc[i];
        pl[(ks * 16 + rq * 4 + i) * 33 + bp] = t.f.x + t.f.y;
    }
}

__device__ __forceinline__ float4 cell_sum4(const float* pl, int cu, int cb)
{
    float4 s = make_float4(0.f, 0.f, 0.f, 0.f);
#pragma unroll
    for (int k = 0; k < 4; ++k) {
        const float* pb = pl + (k * 16) * 33 + cb;
        s.x += pb[(0 + cu) * 33];
        s.y += pb[(4 + cu) * 33];
        s.z += pb[(8 + cu) * 33];
        s.w += pb[(12 + cu) * 33];
    }
    return s;
}

__device__ __forceinline__ float lstm_cell(float4 g, float& c)
{
    float ig = 1.f / (1.f + __expf(-g.x));
    float fg = 1.f / (1.f + __expf(-g.y));
    float gv = tanhf(g.z);
    float og = 1.f / (1.f + __expf(-g.w));
    c = fg * c + ig * gv;
    return og * tanhf(c);
}

// ------------------- fused 3-layer wavefront recurrence ---------------------
// smem: buf1/2/3 [32 b][512 k] (64KB each, per-b octet swizzle) + 3 partials
#define FSMEM ((3 * HH * BB + 3 * PLSZ) * 4)
__global__ __launch_bounds__(512, 1) void fused_rec_kernel(
    const float* __restrict__ xp,
    const float* __restrict__ whh1,
    const float* __restrict__ wih2, const float* __restrict__ whh2,
    const float* __restrict__ b2,
    const float* __restrict__ wih3, const float* __restrict__ whh3,
    const float* __restrict__ b3)
{
    extern __shared__ float sm[];
    float* buf1 = sm;
    float* buf2 = sm + HH * BB;
    float* buf3 = sm + 2 * HH * BB;
    float* pA   = sm + 3 * HH * BB;
    float* pB   = pA + PLSZ;
    float* pC   = pB + PLSZ;

    const int tid = threadIdx.x;
    const int wp  = tid >> 5;
    const int ks  = wp >> 2;          // k-slice 0..3
    const int rq  = wp & 3;           // row quad 0..3 (= gate)
    const int bp  = tid & 31;         // batch 0..31
    const int swz = bp & 7;
    const int u4  = blockIdx.x * 4;

    // weight bases: rows rq*HH + u4 + 0..3, this thread's k-window
    const float* wA = whh1 + (rq * HH + u4) * 512 + ks * 128;
    const float* wB = ((ks < 2) ? wih2 : whh2) + (rq * HH + u4) * 512
                      + (ks & 1) * 256;
    const float* wC = ((ks < 2) ? wih3 : whh3) + (rq * HH + u4) * 512
                      + (ks & 1) * 256;
    // h smem row bases
    const float* hA = buf1 + bp * 512 + ks * 128;
    const float* hB = ((ks < 2) ? buf1 : buf2) + bp * 512 + (ks & 1) * 256;
    const float* hC = ((ks < 2) ? buf2 : buf3) + bp * 512 + (ks & 1) * 256;

    // cell mapping: three 128-thread sets
    const int lset = tid >> 7;            // 0..3 (set 3 idle in cells)
    const int cu = (tid & 127) >> 5;
    const int cb = tid & 31;
    const int cunit = u4 + cu;
    float cst = 0.f, h3sum = 0.f;
    float cbias[4] = {0.f, 0.f, 0.f, 0.f};
    if (lset == 1) {
#pragma unroll
        for (int g = 0; g < 4; ++g) cbias[g] = b2[g * HH + cunit];
    } else if (lset == 2) {
#pragma unroll
        for (int g = 0; g < 4; ++g) cbias[g] = b3[g * HH + cunit];
    }

    // staging: thread covers (b = bseg*8+j, granule k4c) for each buffer
    const int k4c  = tid & 127;
    const int bseg = tid >> 7;
    const unsigned sb1 = (unsigned)__cvta_generic_to_shared(buf1);
    const unsigned sb2 = (unsigned)__cvta_generic_to_shared(buf2);
    const unsigned sb3 = (unsigned)__cvta_generic_to_shared(buf3);

    ull acc[4];

    for (int slot = 0; slot < NSLOT; ++slot) {
        const int rdp = (slot + 1) & 1;
        const int wrp = slot & 1;
        const bool v1 = slot < TT;
        const bool v2 = (slot >= 1) && (slot < TT + 1);
        const bool v3 = slot >= 2;

        // ---- stage h1, then h2+h3 (separate commit groups) ----
        {
            const char* s1 = (const char*)(g_hb1[rdp]);
            const char* s2 = (const char*)(g_hb2[rdp]);
            const char* s3 = (const char*)(g_hb3[rdp]);
#pragma unroll
            for (int j = 0; j < 8; ++j) {
                int b = bseg * 8 + j;
                unsigned doff = (unsigned)((b * 128 +
                    ((k4c & ~7) | ((k4c & 7) ^ (b & 7)))) * 16);
                unsigned soff = (unsigned)((b * 128 + k4c) * 16);
                CP_ASYNC16(sb1 + doff, s1 + soff);
            }
            CP_COMMIT();
#pragma unroll
            for (int j = 0; j < 8; ++j) {
                int b = bseg * 8 + j;
                unsigned doff = (unsigned)((b * 128 +
                    ((k4c & ~7) | ((k4c & 7) ^ (b & 7)))) * 16);
                unsigned soff = (unsigned)((b * 128 + k4c) * 16);
                CP_ASYNC16(sb2 + doff, s2 + soff);
            }
            CP_COMMIT();
#pragma unroll
            for (int j = 0; j < 8; ++j) {
                int b = bseg * 8 + j;
                unsigned doff = (unsigned)((b * 128 +
                    ((k4c & ~7) | ((k4c & 7) ^ (b & 7)))) * 16);
                unsigned soff = (unsigned)((b * 128 + k4c) * 16);
                CP_ASYNC16(sb3 + doff, s3 + soff);
            }
            CP_COMMIT();
        }
        // xp prefetch for layer-1 cells (tid 0..127)
        float xg0 = 0.f, xg1 = 0.f, xg2 = 0.f, xg3 = 0.f;
        if (v1 && lset == 0) {
            const float* xb = xp + (cb * TT + slot) * G4 + cunit;
            xg0 = __ldg(xb);
            xg1 = __ldg(xb + HH);
            xg2 = __ldg(xb + 2 * HH);
            xg3 = __ldg(xb + 3 * HH);
        }

        // ---- GEMM A (needs buf1 only) ----
        CP_WAIT(2);
        __syncthreads();
        if (v1) {
            gphase(acc, wA, hA, swz, 32);
            store_part4(pA, acc, ks, rq, bp);
        }
        // ---- GEMM B (buf1 + buf2) ----
        CP_WAIT(1);
        __syncthreads();
        if (v2) {
            gphase(acc, wB, hB, swz, 64);
            store_part4(pB, acc, ks, rq, bp);
        }
        // ---- GEMM C (buf2 + buf3) ----
        CP_WAIT(0);
        __syncthreads();
        if (v3) {
            gphase(acc, wC, hC, swz, 64);
            store_part4(pC, acc, ks, rq, bp);
        }
        __syncthreads();

        // ---- cells: three layers on disjoint 128-thread sets ----
        if (lset == 0 && v1) {
            float4 g = cell_sum4(pA, cu, cb);
            g.x += xg0; g.y += xg1; g.z += xg2; g.w += xg3;
            float hv = lstm_cell(g, cst);
            __stcg(&g_hb1[wrp][cb * HH + cunit], hv);
        } else if (lset == 1 && v2) {
            float4 g = cell_sum4(pB, cu, cb);
            g.x += cbias[0]; g.y += cbias[1]; g.z += cbias[2]; g.w += cbias[3];
            float hv = lstm_cell(g, cst);
            __stcg(&g_hb2[wrp][cb * HH + cunit], hv);
        } else if (lset == 2 && v3) {
            float4 g = cell_sum4(pC, cu, cb);
            g.x += cbias[0]; g.y += cbias[1]; g.z += cbias[2]; g.w += cbias[3];
            float hv = lstm_cell(g, cst);
            __stcg(&g_hb3[wrp][cb * HH + cunit], hv);
            h3sum += hv;
        }

        grid_bar2(slot);
    }
    if (lset == 2)
        g_feat[cb * HH + cunit] = h3sum * (1.f / 512.f);
}

// --------------------------------- head ------------------------------------
__global__ __launch_bounds__(64) void head_kernel(
    const float* __restrict__ hw, const float* __restrict__ hb,
    float* __restrict__ outp)
{
    const int c = blockIdx.x, b = blockIdx.y;
    float s = 0.f;
    for (int k = threadIdx.x; k < HH; k += 64)
        s += g_feat[b * HH + k] * hw[c * HH + k];
    __shared__ float red[2];
#pragma unroll
    for (int o = 16; o; o >>= 1) s += __shfl_down_sync(0xffffffffu, s, o);
    if ((threadIdx.x & 31) == 0) red[threadIdx.x >> 5] = s;
    __syncthreads();
    if (threadIdx.x == 0) outp[b * NCLS + c] = red[0] + red[1] + hb[c];
}

// ------------------------------ launcher -----------------------------------
extern "C" void kernel_launch(void* const* d_in, const int* in_sizes, int n_in,
                              void* d_out, int out_size)
{
    const float* x_emg  = (const float*)d_in[0];
    const float* conv_w = (const float*)d_in[1];
    const float* gamma  = (const float*)d_in[2];
    const float* beta   = (const float*)d_in[3];
    const float *w_ih[3], *w_hh[3], *bi[3], *head_w, *head_b;

    if (in_sizes[4] == 4 * HH * FF) {          // signature order
        for (int l = 0; l < 3; ++l) {
            w_ih[l] = (const float*)d_in[4 + 3 * l];
            w_hh[l] = (const float*)d_in[5 + 3 * l];
            bi[l]   = (const float*)d_in[6 + 3 * l];
        }
        head_w = (const float*)d_in[13];
        head_b = (const float*)d_in[14];
    } else {                                    // dict order
        head_w = (const float*)d_in[4];
        head_b = (const float*)d_in[5];
        for (int l = 0; l < 3; ++l) {
            w_ih[l] = (const float*)d_in[6 + 3 * l];
            w_hh[l] = (const float*)d_in[7 + 3 * l];
            bi[l]   = (const float*)d_in[8 + 3 * l];
        }
    }
    float* out = (float*)d_out;

    cudaFuncSetAttribute(conv_kernel,
        cudaFuncAttributeMaxDynamicSharedMemorySize, CONV_SMEM);
    cudaFuncSetAttribute(fused_rec_kernel,
        cudaFuncAttributeMaxDynamicSharedMemorySize, FSMEM);

    float* g_xp_p;   cudaGetSymbolAddress((void**)&g_xp_p, g_xp);
    float* g_xt_p;   cudaGetSymbolAddress((void**)&g_xt_p, g_xt);

    conv_kernel<<<dim3(TT / 128, BB), 256, CONV_SMEM>>>(x_emg, conv_w);
    gn_stats_kernel<<<BB * GG, 256>>>();
    gn_apply_kernel<<<dim3(TT / 32, FF / 32, BB), 256>>>(gamma, beta);

    gemm_kernel<<<dim3(G4 / 64, BB * TT / 64), 256>>>(
        g_xt_p, w_ih[0], bi[0], g_xp_p, FF);

    zero_h_kernel<<<128, 256>>>();
    fused_rec_kernel<<<RNB, 512, FSMEM>>>(
        g_xp_p, w_hh[0], w_ih[1], w_hh[1], bi[1], w_ih[2], w_hh[2], bi[2]);

    head_kernel<<<dim3(NCLS, BB), 64>>>(head_w, head_b, out);
}